// round 3
// baseline (speedup 1.0000x reference)
#include <cuda_runtime.h>
#include <cstdint>

#define BB 32
#define TT 4096
#define DD 512
#define GG 8
#define OO 512
#define NC 32           // chunks over T
#define TC (TT/NC)      // 128 tokens per chunk

// Scratch (allocation-free: __device__ globals). Fully overwritten every launch.
__device__ float g_psum[NC * BB * GG * DD];   // 16.8 MB partial sums
__device__ int   g_pcnt[NC * BB * GG];        // partial counts
__device__ float g_mean[BB * GG * DD];        // means [B,G,D]

// ---------------------------------------------------------------------------
// Kernel 1: per-(chunk, batch) partial group sums.
// Block = (chunk c, batch b), 128 threads, each thread owns one float4 D-slice.
// Warp 0 compacts valid token indices into per-group lists (ballot, t-order,
// deterministic). Then each thread streams only VALID rows per group into
// registers -> ~50% of batch bytes never touch HBM.
// ---------------------------------------------------------------------------
__global__ __launch_bounds__(128) void k_partial(const float* __restrict__ batch,
                                                 const int* __restrict__ types,
                                                 const unsigned int* __restrict__ pad)
{
    __shared__ int            s_type[TC];
    __shared__ unsigned char  s_val[TC];
    __shared__ unsigned short s_list[GG][TC];
    __shared__ int            s_cnt[GG];

    const int c   = blockIdx.x;
    const int b   = blockIdx.y;
    const int tid = threadIdx.x;
    const int t0  = c * TC;

    s_type[tid] = types[t0 + tid];
    // mask is a 32-bit word (int32 0/1 or float32 0.0/1.0); nonzero bits = padded
    s_val[tid]  = (pad[b * TT + t0 + tid] == 0u);   // valid = not padded
    __syncthreads();

    if (tid < 32) {
        int cnt[GG];
        #pragma unroll
        for (int g = 0; g < GG; g++) cnt[g] = 0;
        const unsigned lt = (tid == 0) ? 0u : ((1u << tid) - 1u);
        #pragma unroll
        for (int r = 0; r < TC / 32; r++) {
            const int  t  = r * 32 + tid;
            const int  gt = s_type[t];
            const bool v  = (s_val[t] != 0);
            #pragma unroll
            for (int g = 0; g < GG; g++) {
                const unsigned m = __ballot_sync(0xffffffffu, v && (gt == g));
                if (v && (gt == g))
                    s_list[g][cnt[g] + __popc(m & lt)] = (unsigned short)t;
                cnt[g] += __popc(m);   // uniform across lanes
            }
        }
        if (tid == 0) {
            #pragma unroll
            for (int g = 0; g < GG; g++) s_cnt[g] = cnt[g];
        }
    }
    __syncthreads();

    // bp2[t*128] = float4 slice (tid) of row (b, t0+t)
    const float4* bp2 = reinterpret_cast<const float4*>(batch)
                      + (size_t)b * TT * (DD / 4) + (size_t)t0 * (DD / 4) + tid;
    float4* outp = reinterpret_cast<float4*>(g_psum)
                 + (size_t)(c * BB + b) * GG * (DD / 4);

    #pragma unroll 1
    for (int g = 0; g < GG; g++) {
        const int n = s_cnt[g];
        float4 a0 = make_float4(0.f, 0.f, 0.f, 0.f);
        float4 a1 = make_float4(0.f, 0.f, 0.f, 0.f);
        int i = 0;
        for (; i + 4 <= n; i += 4) {
            const int ta = s_list[g][i];
            const int tb = s_list[g][i + 1];
            const int tc2 = s_list[g][i + 2];
            const int td = s_list[g][i + 3];
            const float4 v0 = bp2[ta * 128];
            const float4 v1 = bp2[tb * 128];
            const float4 v2 = bp2[tc2 * 128];
            const float4 v3 = bp2[td * 128];
            a0.x += v0.x; a0.y += v0.y; a0.z += v0.z; a0.w += v0.w;
            a1.x += v1.x; a1.y += v1.y; a1.z += v1.z; a1.w += v1.w;
            a0.x += v2.x; a0.y += v2.y; a0.z += v2.z; a0.w += v2.w;
            a1.x += v3.x; a1.y += v3.y; a1.z += v3.z; a1.w += v3.w;
        }
        for (; i < n; i++) {
            const float4 v = bp2[(int)s_list[g][i] * 128];
            a0.x += v.x; a0.y += v.y; a0.z += v.z; a0.w += v.w;
        }
        a0.x += a1.x; a0.y += a1.y; a0.z += a1.z; a0.w += a1.w;
        outp[g * (DD / 4) + tid] = a0;
    }
    if (tid < GG) g_pcnt[(c * BB + b) * GG + tid] = s_cnt[tid];
}

// ---------------------------------------------------------------------------
// Kernel 2: reduce partials over chunks, divide by count (0 if empty group).
// Block = (b*G+g), 128 threads (one float4 slice each).
// ---------------------------------------------------------------------------
__global__ __launch_bounds__(128) void k_reduce()
{
    const int bg  = blockIdx.x;     // b*GG+g
    const int tid = threadIdx.x;

    __shared__ float s_inv;
    if (tid == 0) {
        int cnt = 0;
        #pragma unroll
        for (int c = 0; c < NC; c++) cnt += g_pcnt[c * BB * GG + bg];
        s_inv = (cnt > 0) ? (1.0f / (float)cnt) : 0.0f;
    }
    __syncthreads();

    const float4* p = reinterpret_cast<const float4*>(g_psum) + (size_t)bg * (DD / 4) + tid;
    float4 s = make_float4(0.f, 0.f, 0.f, 0.f);
    #pragma unroll
    for (int c = 0; c < NC; c++) {
        const float4 v = p[(size_t)c * BB * GG * (DD / 4)];
        s.x += v.x; s.y += v.y; s.z += v.z; s.w += v.w;
    }
    const float inv = s_inv;
    reinterpret_cast<float4*>(g_mean)[(size_t)bg * (DD / 4) + tid] =
        make_float4(s.x * inv, s.y * inv, s.z * inv, s.w * inv);
}

// ---------------------------------------------------------------------------
// Kernel 3: out[b,g,o] = dot(mean[b,g,:], W[g,:,o]) + bias[g,o]
// Grid = (16 o-tiles of 32, G). 256 threads: o = tid&31, bh = tid>>5 -> 4 b's.
// Means staged transposed in smem (pad 33, conflict-free), broadcast reads.
// ---------------------------------------------------------------------------
__global__ __launch_bounds__(256) void k_gemm(const float* __restrict__ W,
                                              const float* __restrict__ bias,
                                              float* __restrict__ out)
{
    const int ot  = blockIdx.x;
    const int g   = blockIdx.y;
    const int tid = threadIdx.x;
    const int o   = ot * 32 + (tid & 31);
    const int bh  = tid >> 5;            // 0..7 -> b = bh*4 + j

    __shared__ float sm[128 * 33];

    float acc0 = 0.f, acc1 = 0.f, acc2 = 0.f, acc3 = 0.f;

    for (int d0 = 0; d0 < DD; d0 += 128) {
        __syncthreads();
        // stage mean[b][g][d0+dc] -> sm[dc*33 + b]; gmem-coalesced, smem conflict-free
        for (int idx = tid; idx < 32 * 128; idx += 256) {
            const int dc = idx & 127;
            const int b  = idx >> 7;
            sm[dc * 33 + b] = g_mean[(b * GG + g) * DD + d0 + dc];
        }
        __syncthreads();

        const float* wp = W + (size_t)(g * DD + d0) * OO + o;
        #pragma unroll 4
        for (int dc = 0; dc < 128; dc++) {
            const float w = wp[(size_t)dc * OO];
            const float* mrow = sm + dc * 33 + bh * 4;
            acc0 += mrow[0] * w;
            acc1 += mrow[1] * w;
            acc2 += mrow[2] * w;
            acc3 += mrow[3] * w;
        }
    }

    const float bi = bias[g * OO + o];
    out[((bh * 4 + 0) * GG + g) * OO + o] = acc0 + bi;
    out[((bh * 4 + 1) * GG + g) * OO + o] = acc1 + bi;
    out[((bh * 4 + 2) * GG + g) * OO + o] = acc2 + bi;
    out[((bh * 4 + 3) * GG + g) * OO + o] = acc3 + bi;
}

// ---------------------------------------------------------------------------
extern "C" void kernel_launch(void* const* d_in, const int* in_sizes, int n_in,
                              void* d_out, int out_size)
{
    const float*        batch = (const float*)d_in[0];          // [B,T,D] f32
    const float*        W     = (const float*)d_in[1];          // [G,D,OUT] f32
    const float*        bias  = (const float*)d_in[2];          // [G,OUT] f32
    const int*          types = (const int*)d_in[3];            // [T] i32
    const unsigned int* pad   = (const unsigned int*)d_in[4];   // [B,T] mask, 32-bit 0/nonzero
    float*              out   = (float*)d_out;                  // [B,G,OUT] f32

    k_partial<<<dim3(NC, BB), 128>>>(batch, types, pad);
    k_reduce<<<BB * GG, 128>>>();
    k_gemm<<<dim3(OO / 32, GG), 256>>>(W, bias, out);
}

// round 4
// speedup vs baseline: 1.7071x; 1.7071x over previous
#include <cuda_runtime.h>
#include <cstdint>

#define BB 32
#define TT 4096
#define DD 512
#define GG 8
#define OO 512
#define NC 32           // chunks over T
#define TC (TT/NC)      // 128 tokens per chunk

// Scratch (allocation-free: __device__ globals). Fully overwritten every launch.
__device__ float g_psum[NC * BB * GG * DD];   // 16.8 MB partial sums
__device__ int   g_pcnt[NC * BB * GG];        // partial counts
__device__ float g_mean[BB * GG * DD];        // means [B,G,D]

// ---------------------------------------------------------------------------
// Kernel 1: per-(chunk, batch) partial group sums. (unchanged: 29.6us, 4.9TB/s)
// ---------------------------------------------------------------------------
__global__ __launch_bounds__(128) void k_partial(const float* __restrict__ batch,
                                                 const int* __restrict__ types,
                                                 const unsigned int* __restrict__ pad)
{
    __shared__ int            s_type[TC];
    __shared__ unsigned char  s_val[TC];
    __shared__ unsigned short s_list[GG][TC];
    __shared__ int            s_cnt[GG];

    const int c   = blockIdx.x;
    const int b   = blockIdx.y;
    const int tid = threadIdx.x;
    const int t0  = c * TC;

    s_type[tid] = types[t0 + tid];
    s_val[tid]  = (pad[b * TT + t0 + tid] == 0u);   // valid = not padded
    __syncthreads();

    if (tid < 32) {
        int cnt[GG];
        #pragma unroll
        for (int g = 0; g < GG; g++) cnt[g] = 0;
        const unsigned lt = (tid == 0) ? 0u : ((1u << tid) - 1u);
        #pragma unroll
        for (int r = 0; r < TC / 32; r++) {
            const int  t  = r * 32 + tid;
            const int  gt = s_type[t];
            const bool v  = (s_val[t] != 0);
            #pragma unroll
            for (int g = 0; g < GG; g++) {
                const unsigned m = __ballot_sync(0xffffffffu, v && (gt == g));
                if (v && (gt == g))
                    s_list[g][cnt[g] + __popc(m & lt)] = (unsigned short)t;
                cnt[g] += __popc(m);   // uniform across lanes
            }
        }
        if (tid == 0) {
            #pragma unroll
            for (int g = 0; g < GG; g++) s_cnt[g] = cnt[g];
        }
    }
    __syncthreads();

    const float4* bp2 = reinterpret_cast<const float4*>(batch)
                      + (size_t)b * TT * (DD / 4) + (size_t)t0 * (DD / 4) + tid;
    float4* outp = reinterpret_cast<float4*>(g_psum)
                 + (size_t)(c * BB + b) * GG * (DD / 4);

    #pragma unroll 1
    for (int g = 0; g < GG; g++) {
        const int n = s_cnt[g];
        float4 a0 = make_float4(0.f, 0.f, 0.f, 0.f);
        float4 a1 = make_float4(0.f, 0.f, 0.f, 0.f);
        int i = 0;
        for (; i + 4 <= n; i += 4) {
            const int ta = s_list[g][i];
            const int tb = s_list[g][i + 1];
            const int tc2 = s_list[g][i + 2];
            const int td = s_list[g][i + 3];
            const float4 v0 = bp2[ta * 128];
            const float4 v1 = bp2[tb * 128];
            const float4 v2 = bp2[tc2 * 128];
            const float4 v3 = bp2[td * 128];
            a0.x += v0.x; a0.y += v0.y; a0.z += v0.z; a0.w += v0.w;
            a1.x += v1.x; a1.y += v1.y; a1.z += v1.z; a1.w += v1.w;
            a0.x += v2.x; a0.y += v2.y; a0.z += v2.z; a0.w += v2.w;
            a1.x += v3.x; a1.y += v3.y; a1.z += v3.z; a1.w += v3.w;
        }
        for (; i < n; i++) {
            const float4 v = bp2[(int)s_list[g][i] * 128];
            a0.x += v.x; a0.y += v.y; a0.z += v.z; a0.w += v.w;
        }
        a0.x += a1.x; a0.y += a1.y; a0.z += a1.z; a0.w += a1.w;
        outp[g * (DD / 4) + tid] = a0;
    }
    if (tid < GG) g_pcnt[(c * BB + b) * GG + tid] = s_cnt[tid];
}

// ---------------------------------------------------------------------------
// Kernel 2: reduce partials over chunks, divide by count. (unchanged)
// ---------------------------------------------------------------------------
__global__ __launch_bounds__(128) void k_reduce()
{
    const int bg  = blockIdx.x;     // b*GG+g
    const int tid = threadIdx.x;

    __shared__ float s_inv;
    if (tid == 0) {
        int cnt = 0;
        #pragma unroll
        for (int c = 0; c < NC; c++) cnt += g_pcnt[c * BB * GG + bg];
        s_inv = (cnt > 0) ? (1.0f / (float)cnt) : 0.0f;
    }
    __syncthreads();

    const float4* p = reinterpret_cast<const float4*>(g_psum) + (size_t)bg * (DD / 4) + tid;
    float4 s = make_float4(0.f, 0.f, 0.f, 0.f);
    #pragma unroll
    for (int c = 0; c < NC; c++) {
        const float4 v = p[(size_t)c * BB * GG * (DD / 4)];
        s.x += v.x; s.y += v.y; s.z += v.z; s.w += v.w;
    }
    const float inv = s_inv;
    reinterpret_cast<float4*>(g_mean)[(size_t)bg * (DD / 4) + tid] =
        make_float4(s.x * inv, s.y * inv, s.z * inv, s.w * inv);
}

// ---------------------------------------------------------------------------
// Kernel 3 (REWRITTEN): out[b,g,o] = dot(mean[b,g,:], W[g,:,o]) + bias[g,o]
// Grid = (4 o-tiles of 128, 4 b-octets of 8, G). 256 threads = 8 warps.
// Warp w handles b = bo*8+w over a 128-o tile: lane owns one float4 of o.
// W streamed as LDG.128 along contiguous o, d-loop unrolled x8 -> MLP 8.
// Means staged in smem (16KB), broadcast LDS per d.
// ---------------------------------------------------------------------------
__global__ __launch_bounds__(256) void k_gemm(const float* __restrict__ W,
                                              const float* __restrict__ bias,
                                              float* __restrict__ out)
{
    const int ot   = blockIdx.x;          // o-tile: 128 outputs
    const int bo   = blockIdx.y;          // b-octet
    const int g    = blockIdx.z;
    const int warp = threadIdx.x >> 5;    // 0..7 -> b = bo*8+warp
    const int lane = threadIdx.x & 31;    // float4 column within o-tile

    __shared__ float s_mean[8][DD];       // 16 KB

    // stage means for this b-octet: 1024 float4, 4 per thread, coalesced
    {
        float4* sm4 = reinterpret_cast<float4*>(s_mean);
        const float4* gm4 = reinterpret_cast<const float4*>(g_mean);
        #pragma unroll
        for (int k = 0; k < 4; k++) {
            const int idx = threadIdx.x + k * 256;       // 0..1023
            const int bb  = idx >> 7;                    // 0..7
            const int dd  = idx & 127;                   // float4 index in D
            sm4[idx] = gm4[((size_t)(bo * 8 + bb) * GG + g) * (DD / 4) + dd];
        }
    }
    __syncthreads();

    const float4* W4 = reinterpret_cast<const float4*>(W)
                     + (size_t)g * DD * (OO / 4) + ot * 32 + lane;
    const float* mrow = s_mean[warp];

    float4 acc = make_float4(0.f, 0.f, 0.f, 0.f);

    #pragma unroll 1
    for (int d = 0; d < DD; d += 8) {
        // 8 independent LDG.128 in flight
        float4 w0 = W4[(size_t)(d + 0) * (OO / 4)];
        float4 w1 = W4[(size_t)(d + 1) * (OO / 4)];
        float4 w2 = W4[(size_t)(d + 2) * (OO / 4)];
        float4 w3 = W4[(size_t)(d + 3) * (OO / 4)];
        float4 w4 = W4[(size_t)(d + 4) * (OO / 4)];
        float4 w5 = W4[(size_t)(d + 5) * (OO / 4)];
        float4 w6 = W4[(size_t)(d + 6) * (OO / 4)];
        float4 w7 = W4[(size_t)(d + 7) * (OO / 4)];
        const float m0 = mrow[d + 0], m1 = mrow[d + 1];
        const float m2 = mrow[d + 2], m3 = mrow[d + 3];
        const float m4 = mrow[d + 4], m5 = mrow[d + 5];
        const float m6 = mrow[d + 6], m7 = mrow[d + 7];
        acc.x += m0 * w0.x; acc.y += m0 * w0.y; acc.z += m0 * w0.z; acc.w += m0 * w0.w;
        acc.x += m1 * w1.x; acc.y += m1 * w1.y; acc.z += m1 * w1.z; acc.w += m1 * w1.w;
        acc.x += m2 * w2.x; acc.y += m2 * w2.y; acc.z += m2 * w2.z; acc.w += m2 * w2.w;
        acc.x += m3 * w3.x; acc.y += m3 * w3.y; acc.z += m3 * w3.z; acc.w += m3 * w3.w;
        acc.x += m4 * w4.x; acc.y += m4 * w4.y; acc.z += m4 * w4.z; acc.w += m4 * w4.w;
        acc.x += m5 * w5.x; acc.y += m5 * w5.y; acc.z += m5 * w5.z; acc.w += m5 * w5.w;
        acc.x += m6 * w6.x; acc.y += m6 * w6.y; acc.z += m6 * w6.z; acc.w += m6 * w6.w;
        acc.x += m7 * w7.x; acc.y += m7 * w7.y; acc.z += m7 * w7.z; acc.w += m7 * w7.w;
    }

    const float4 bi = reinterpret_cast<const float4*>(bias)[g * (OO / 4) + ot * 32 + lane];
    const int b = bo * 8 + warp;
    reinterpret_cast<float4*>(out)[((size_t)b * GG + g) * (OO / 4) + ot * 32 + lane] =
        make_float4(acc.x + bi.x, acc.y + bi.y, acc.z + bi.z, acc.w + bi.w);
}

// ---------------------------------------------------------------------------
extern "C" void kernel_launch(void* const* d_in, const int* in_sizes, int n_in,
                              void* d_out, int out_size)
{
    const float*        batch = (const float*)d_in[0];          // [B,T,D] f32
    const float*        W     = (const float*)d_in[1];          // [G,D,OUT] f32
    const float*        bias  = (const float*)d_in[2];          // [G,OUT] f32
    const int*          types = (const int*)d_in[3];            // [T] i32
    const unsigned int* pad   = (const unsigned int*)d_in[4];   // [B,T] mask words
    float*              out   = (float*)d_out;                  // [B,G,OUT] f32

    k_partial<<<dim3(NC, BB), 128>>>(batch, types, pad);
    k_reduce<<<BB * GG, 128>>>();
    k_gemm<<<dim3(OO / 128, BB / 8, GG), 256>>>(W, bias, out);
}

// round 5
// speedup vs baseline: 4.0877x; 2.3945x over previous
#include <cuda_runtime.h>
#include <cstdint>

#define BB 32
#define TT 4096
#define DD 512
#define GG 8
#define OO 512
#define NC 32           // chunks over T
#define TC (TT/NC)      // 128 tokens per chunk

// Scratch (allocation-free: __device__ globals). Fully overwritten every launch.
__device__ float g_psum[NC * BB * GG * DD];   // 16.8 MB partial sums
__device__ int   g_pcnt[NC * BB * GG];        // partial counts

// ---------------------------------------------------------------------------
// Kernel 1: per-(chunk, batch) partial group sums. (unchanged: 28.8us, 5TB/s)
// ---------------------------------------------------------------------------
__global__ __launch_bounds__(128) void k_partial(const float* __restrict__ batch,
                                                 const int* __restrict__ types,
                                                 const unsigned int* __restrict__ pad)
{
    __shared__ int            s_type[TC];
    __shared__ unsigned char  s_val[TC];
    __shared__ unsigned short s_list[GG][TC];
    __shared__ int            s_cnt[GG];

    const int c   = blockIdx.x;
    const int b   = blockIdx.y;
    const int tid = threadIdx.x;
    const int t0  = c * TC;

    s_type[tid] = types[t0 + tid];
    s_val[tid]  = (pad[b * TT + t0 + tid] == 0u);   // valid = not padded
    __syncthreads();

    if (tid < 32) {
        int cnt[GG];
        #pragma unroll
        for (int g = 0; g < GG; g++) cnt[g] = 0;
        const unsigned lt = (tid == 0) ? 0u : ((1u << tid) - 1u);
        #pragma unroll
        for (int r = 0; r < TC / 32; r++) {
            const int  t  = r * 32 + tid;
            const int  gt = s_type[t];
            const bool v  = (s_val[t] != 0);
            #pragma unroll
            for (int g = 0; g < GG; g++) {
                const unsigned m = __ballot_sync(0xffffffffu, v && (gt == g));
                if (v && (gt == g))
                    s_list[g][cnt[g] + __popc(m & lt)] = (unsigned short)t;
                cnt[g] += __popc(m);   // uniform across lanes
            }
        }
        if (tid == 0) {
            #pragma unroll
            for (int g = 0; g < GG; g++) s_cnt[g] = cnt[g];
        }
    }
    __syncthreads();

    const float4* bp2 = reinterpret_cast<const float4*>(batch)
                      + (size_t)b * TT * (DD / 4) + (size_t)t0 * (DD / 4) + tid;
    float4* outp = reinterpret_cast<float4*>(g_psum)
                 + (size_t)(c * BB + b) * GG * (DD / 4);

    #pragma unroll 1
    for (int g = 0; g < GG; g++) {
        const int n = s_cnt[g];
        float4 a0 = make_float4(0.f, 0.f, 0.f, 0.f);
        float4 a1 = make_float4(0.f, 0.f, 0.f, 0.f);
        int i = 0;
        for (; i + 4 <= n; i += 4) {
            const int ta = s_list[g][i];
            const int tb = s_list[g][i + 1];
            const int tc2 = s_list[g][i + 2];
            const int td = s_list[g][i + 3];
            const float4 v0 = bp2[ta * 128];
            const float4 v1 = bp2[tb * 128];
            const float4 v2 = bp2[tc2 * 128];
            const float4 v3 = bp2[td * 128];
            a0.x += v0.x; a0.y += v0.y; a0.z += v0.z; a0.w += v0.w;
            a1.x += v1.x; a1.y += v1.y; a1.z += v1.z; a1.w += v1.w;
            a0.x += v2.x; a0.y += v2.y; a0.z += v2.z; a0.w += v2.w;
            a1.x += v3.x; a1.y += v3.y; a1.z += v3.z; a1.w += v3.w;
        }
        for (; i < n; i++) {
            const float4 v = bp2[(int)s_list[g][i] * 128];
            a0.x += v.x; a0.y += v.y; a0.z += v.z; a0.w += v.w;
        }
        a0.x += a1.x; a0.y += a1.y; a0.z += a1.z; a0.w += a1.w;
        outp[g * (DD / 4) + tid] = a0;
    }
    if (tid < GG) g_pcnt[(c * BB + b) * GG + tid] = s_cnt[tid];
}

// ---------------------------------------------------------------------------
// Kernel 2 (FUSED reduce+gemm): grid (4 o-tiles x 4 b-octets x G), 256 thr.
// Stage A: reduce psum over chunks -> s_mean[8][512] (psum is L2-resident).
// Stage B: warp w owns d-slice [64w,64w+64); register-blocks all 8 b's so
//          every W address is loaded by exactly ONE warp (no 8x L2 re-read).
//          Cross-warp partial accs reduced via smem.
// ---------------------------------------------------------------------------
__global__ __launch_bounds__(256) void k_tail(const float* __restrict__ W,
                                              const float* __restrict__ bias,
                                              float* __restrict__ out)
{
    const int ot   = blockIdx.x;          // 128-output o-tile
    const int bo   = blockIdx.y;          // batch octet
    const int g    = blockIdx.z;
    const int tid  = threadIdx.x;
    const int warp = tid >> 5;            // 0..7 -> d-slice
    const int lane = tid & 31;            // o-float4 within tile

    __shared__ float s_mean[8][DD];       // 16 KB
    __shared__ union {                    // 32 KB, time-multiplexed
        float  inv[8];                    //   early: 1/count per b
        float4 part[8][8][32];            //   late: [warp][b][lane] partials
    } u;

    // counts -> 1/count
    if (tid < 8) {
        const int b = bo * 8 + tid;
        int cnt = 0;
        #pragma unroll
        for (int c = 0; c < NC; c++) cnt += g_pcnt[(c * BB + b) * GG + g];
        u.inv[tid] = (cnt > 0) ? (1.0f / (float)cnt) : 0.0f;
    }

    // Stage A: reduce psum over chunks. 1024 float4 outputs, 4 per thread.
    const float4* ps4 = reinterpret_cast<const float4*>(g_psum);
    float4* sm4 = reinterpret_cast<float4*>(s_mean);
    float4 red[4];
    #pragma unroll
    for (int k = 0; k < 4; k++) {
        const int idx = tid + k * 256;                 // 0..1023
        const int bb  = idx >> 7;                      // 0..7
        const int d4  = idx & 127;
        const size_t base = ((size_t)(bo * 8 + bb) * GG + g) * (DD / 4) + d4;
        float4 s = make_float4(0.f, 0.f, 0.f, 0.f);
        #pragma unroll
        for (int c = 0; c < NC; c++) {
            const float4 v = ps4[base + (size_t)c * BB * GG * (DD / 4)];
            s.x += v.x; s.y += v.y; s.z += v.z; s.w += v.w;
        }
        red[k] = s;
    }
    __syncthreads();   // u.inv ready
    #pragma unroll
    for (int k = 0; k < 4; k++) {
        const int idx = tid + k * 256;
        const float inv = u.inv[idx >> 7];
        sm4[idx] = make_float4(red[k].x * inv, red[k].y * inv,
                               red[k].z * inv, red[k].w * inv);
    }
    __syncthreads();   // means final; u.inv dead -> u.part may be written

    // Stage B: per-warp d-slice GEMM, register-blocked over 8 b's.
    const float4* W4 = reinterpret_cast<const float4*>(W)
                     + (size_t)g * DD * (OO / 4) + ot * 32 + lane;
    float4 acc[8];
    #pragma unroll
    for (int b = 0; b < 8; b++) acc[b] = make_float4(0.f, 0.f, 0.f, 0.f);

    const int d0 = warp * 64;
    #pragma unroll 4
    for (int dd = 0; dd < 64; dd++) {
        const int d = d0 + dd;
        const float4 w = W4[(size_t)d * (OO / 4)];
        #pragma unroll
        for (int b = 0; b < 8; b++) {
            const float m = s_mean[b][d];
            acc[b].x += m * w.x; acc[b].y += m * w.y;
            acc[b].z += m * w.z; acc[b].w += m * w.w;
        }
    }

    #pragma unroll
    for (int b = 0; b < 8; b++) u.part[warp][b][lane] = acc[b];
    __syncthreads();

    // Final cross-warp reduce: thread t -> (b = t>>5, lane = t&31)
    {
        const int b = tid >> 5;
        const int l = tid & 31;
        float4 s = make_float4(0.f, 0.f, 0.f, 0.f);
        #pragma unroll
        for (int w = 0; w < 8; w++) {
            const float4 v = u.part[w][b][l];
            s.x += v.x; s.y += v.y; s.z += v.z; s.w += v.w;
        }
        const float4 bi = reinterpret_cast<const float4*>(bias)[g * (OO / 4) + ot * 32 + l];
        const size_t obg = (size_t)((bo * 8 + b) * GG + g);
        reinterpret_cast<float4*>(out)[obg * (OO / 4) + ot * 32 + l] =
            make_float4(s.x + bi.x, s.y + bi.y, s.z + bi.z, s.w + bi.w);
    }
}

// ---------------------------------------------------------------------------
extern "C" void kernel_launch(void* const* d_in, const int* in_sizes, int n_in,
                              void* d_out, int out_size)
{
    const float*        batch = (const float*)d_in[0];          // [B,T,D] f32
    const float*        W     = (const float*)d_in[1];          // [G,D,OUT] f32
    const float*        bias  = (const float*)d_in[2];          // [G,OUT] f32
    const int*          types = (const int*)d_in[3];            // [T] i32
    const unsigned int* pad   = (const unsigned int*)d_in[4];   // [B,T] mask words
    float*              out   = (float*)d_out;                  // [B,G,OUT] f32

    k_partial<<<dim3(NC, BB), 128>>>(batch, types, pad);
    k_tail<<<dim3(OO / 128, BB / 8, GG), 256>>>(W, bias, out);
}

// round 6
// speedup vs baseline: 5.1493x; 1.2597x over previous
#include <cuda_runtime.h>
#include <cstdint>

#define BB 32
#define TT 4096
#define DD 512
#define GG 8
#define OO 512
#define NC 32           // chunks over T
#define TC (TT/NC)      // 128 tokens per chunk

// Scratch (allocation-free: __device__ globals). Fully overwritten every launch.
__device__ float g_psum[NC * BB * GG * DD];   // 16.8 MB partial sums
__device__ int   g_pcnt[NC * BB * GG];        // partial counts
__device__ float g_mean[BB * GG * DD];        // means [B,G,D]

// ---------------------------------------------------------------------------
// Kernel 1: per-(chunk, batch) partial group sums.
// 8-deep gather unroll (MLP 8), streaming loads (.cs) on batch (zero reuse).
// ---------------------------------------------------------------------------
__global__ __launch_bounds__(128) void k_partial(const float* __restrict__ batch,
                                                 const int* __restrict__ types,
                                                 const unsigned int* __restrict__ pad)
{
    __shared__ int            s_type[TC];
    __shared__ unsigned char  s_val[TC];
    __shared__ unsigned short s_list[GG][TC];
    __shared__ int            s_cnt[GG];

    const int c   = blockIdx.x;
    const int b   = blockIdx.y;
    const int tid = threadIdx.x;
    const int t0  = c * TC;

    s_type[tid] = types[t0 + tid];
    s_val[tid]  = (pad[b * TT + t0 + tid] == 0u);   // valid = not padded
    __syncthreads();

    if (tid < 32) {
        int cnt[GG];
        #pragma unroll
        for (int g = 0; g < GG; g++) cnt[g] = 0;
        const unsigned lt = (tid == 0) ? 0u : ((1u << tid) - 1u);
        #pragma unroll
        for (int r = 0; r < TC / 32; r++) {
            const int  t  = r * 32 + tid;
            const int  gt = s_type[t];
            const bool v  = (s_val[t] != 0);
            #pragma unroll
            for (int g = 0; g < GG; g++) {
                const unsigned m = __ballot_sync(0xffffffffu, v && (gt == g));
                if (v && (gt == g))
                    s_list[g][cnt[g] + __popc(m & lt)] = (unsigned short)t;
                cnt[g] += __popc(m);   // uniform across lanes
            }
        }
        if (tid == 0) {
            #pragma unroll
            for (int g = 0; g < GG; g++) s_cnt[g] = cnt[g];
        }
    }
    __syncthreads();

    const float4* bp2 = reinterpret_cast<const float4*>(batch)
                      + (size_t)b * TT * (DD / 4) + (size_t)t0 * (DD / 4) + tid;
    float4* outp = reinterpret_cast<float4*>(g_psum)
                 + (size_t)(c * BB + b) * GG * (DD / 4);

    #pragma unroll 1
    for (int g = 0; g < GG; g++) {
        const int n = s_cnt[g];
        float4 a0 = make_float4(0.f, 0.f, 0.f, 0.f);
        float4 a1 = make_float4(0.f, 0.f, 0.f, 0.f);
        int i = 0;
        for (; i + 8 <= n; i += 8) {
            float4 v0 = __ldcs(&bp2[(int)s_list[g][i + 0] * 128]);
            float4 v1 = __ldcs(&bp2[(int)s_list[g][i + 1] * 128]);
            float4 v2 = __ldcs(&bp2[(int)s_list[g][i + 2] * 128]);
            float4 v3 = __ldcs(&bp2[(int)s_list[g][i + 3] * 128]);
            float4 v4 = __ldcs(&bp2[(int)s_list[g][i + 4] * 128]);
            float4 v5 = __ldcs(&bp2[(int)s_list[g][i + 5] * 128]);
            float4 v6 = __ldcs(&bp2[(int)s_list[g][i + 6] * 128]);
            float4 v7 = __ldcs(&bp2[(int)s_list[g][i + 7] * 128]);
            a0.x += v0.x; a0.y += v0.y; a0.z += v0.z; a0.w += v0.w;
            a1.x += v1.x; a1.y += v1.y; a1.z += v1.z; a1.w += v1.w;
            a0.x += v2.x; a0.y += v2.y; a0.z += v2.z; a0.w += v2.w;
            a1.x += v3.x; a1.y += v3.y; a1.z += v3.z; a1.w += v3.w;
            a0.x += v4.x; a0.y += v4.y; a0.z += v4.z; a0.w += v4.w;
            a1.x += v5.x; a1.y += v5.y; a1.z += v5.z; a1.w += v5.w;
            a0.x += v6.x; a0.y += v6.y; a0.z += v6.z; a0.w += v6.w;
            a1.x += v7.x; a1.y += v7.y; a1.z += v7.z; a1.w += v7.w;
        }
        for (; i < n; i++) {
            const float4 v = __ldcs(&bp2[(int)s_list[g][i] * 128]);
            a0.x += v.x; a0.y += v.y; a0.z += v.z; a0.w += v.w;
        }
        a0.x += a1.x; a0.y += a1.y; a0.z += a1.z; a0.w += a1.w;
        outp[g * (DD / 4) + tid] = a0;
    }
    if (tid < GG) g_pcnt[(c * BB + b) * GG + tid] = s_cnt[tid];
}

// ---------------------------------------------------------------------------
// Kernel 2: reduce psum -> mean, ONCE (no ot duplication). 256 blocks x 128.
// Each thread: 32 independent 512KB-strided L2 float4 loads (MLP 32).
// ---------------------------------------------------------------------------
__global__ __launch_bounds__(128) void k_mean()
{
    const int bg  = blockIdx.x;     // b*GG+g
    const int tid = threadIdx.x;

    __shared__ float s_inv;
    if (tid == 0) {
        int cnt = 0;
        #pragma unroll
        for (int c = 0; c < NC; c++) cnt += g_pcnt[c * BB * GG + bg];
        s_inv = (cnt > 0) ? (1.0f / (float)cnt) : 0.0f;
    }
    __syncthreads();

    const float4* p = reinterpret_cast<const float4*>(g_psum) + (size_t)bg * (DD / 4) + tid;
    float4 s = make_float4(0.f, 0.f, 0.f, 0.f);
    #pragma unroll
    for (int c = 0; c < NC; c++) {
        const float4 v = p[(size_t)c * BB * GG * (DD / 4)];
        s.x += v.x; s.y += v.y; s.z += v.z; s.w += v.w;
    }
    const float inv = s_inv;
    reinterpret_cast<float4*>(g_mean)[(size_t)bg * (DD / 4) + tid] =
        make_float4(s.x * inv, s.y * inv, s.z * inv, s.w * inv);
}

// ---------------------------------------------------------------------------
// Kernel 3: GEMM. grid (4 ot x 8 bo x 8 g) = 256 blocks, 256 threads.
// Warp w owns d in [64w, 64w+64); register-blocks 4 b's x 1 o-float4.
// Every W address loaded by exactly one warp. Cross-warp reduce via smem.
// ---------------------------------------------------------------------------
__global__ __launch_bounds__(256) void k_gemm(const float* __restrict__ W,
                                              const float* __restrict__ bias,
                                              float* __restrict__ out)
{
    const int ot   = blockIdx.x;          // 128-output o-tile
    const int bo   = blockIdx.y;          // batch quad (4 b)
    const int g    = blockIdx.z;
    const int tid  = threadIdx.x;
    const int warp = tid >> 5;            // d-slice owner
    const int lane = tid & 31;            // o-float4 in tile

    __shared__ float  s_mean[4][DD];      // 8 KB
    __shared__ float4 s_part[8][4][32];   // 16 KB

    // stage means: 4 b x 128 float4 = 512 float4, 2 per thread, coalesced
    {
        float4* sm4 = reinterpret_cast<float4*>(s_mean);
        const float4* gm4 = reinterpret_cast<const float4*>(g_mean);
        #pragma unroll
        for (int k = 0; k < 2; k++) {
            const int idx = tid + k * 256;                 // 0..511
            const int bb  = idx >> 7;                      // 0..3
            const int d4  = idx & 127;
            sm4[idx] = gm4[((size_t)(bo * 4 + bb) * GG + g) * (DD / 4) + d4];
        }
    }
    __syncthreads();

    const float4* W4 = reinterpret_cast<const float4*>(W)
                     + (size_t)g * DD * (OO / 4) + ot * 32 + lane;

    float4 a0 = make_float4(0.f, 0.f, 0.f, 0.f);
    float4 a1 = make_float4(0.f, 0.f, 0.f, 0.f);
    float4 a2 = make_float4(0.f, 0.f, 0.f, 0.f);
    float4 a3 = make_float4(0.f, 0.f, 0.f, 0.f);

    const int d0 = warp * 64;
    #pragma unroll 8
    for (int dd = 0; dd < 64; dd++) {
        const int d = d0 + dd;
        const float4 w = W4[(size_t)d * (OO / 4)];
        const float m0 = s_mean[0][d];
        const float m1 = s_mean[1][d];
        const float m2 = s_mean[2][d];
        const float m3 = s_mean[3][d];
        a0.x += m0 * w.x; a0.y += m0 * w.y; a0.z += m0 * w.z; a0.w += m0 * w.w;
        a1.x += m1 * w.x; a1.y += m1 * w.y; a1.z += m1 * w.z; a1.w += m1 * w.w;
        a2.x += m2 * w.x; a2.y += m2 * w.y; a2.z += m2 * w.z; a2.w += m2 * w.w;
        a3.x += m3 * w.x; a3.y += m3 * w.y; a3.z += m3 * w.z; a3.w += m3 * w.w;
    }

    s_part[warp][0][lane] = a0;
    s_part[warp][1][lane] = a1;
    s_part[warp][2][lane] = a2;
    s_part[warp][3][lane] = a3;
    __syncthreads();

    // Final reduce: threads 0..127 -> (b = tid>>5, lane = tid&31)
    if (tid < 128) {
        const int b = tid >> 5;
        const int l = tid & 31;
        float4 s = make_float4(0.f, 0.f, 0.f, 0.f);
        #pragma unroll
        for (int w = 0; w < 8; w++) {
            const float4 v = s_part[w][b][l];
            s.x += v.x; s.y += v.y; s.z += v.z; s.w += v.w;
        }
        const float4 bi = reinterpret_cast<const float4*>(bias)[g * (OO / 4) + ot * 32 + l];
        const size_t obg = (size_t)((bo * 4 + b) * GG + g);
        reinterpret_cast<float4*>(out)[obg * (OO / 4) + ot * 32 + l] =
            make_float4(s.x + bi.x, s.y + bi.y, s.z + bi.z, s.w + bi.w);
    }
}

// ---------------------------------------------------------------------------
extern "C" void kernel_launch(void* const* d_in, const int* in_sizes, int n_in,
                              void* d_out, int out_size)
{
    const float*        batch = (const float*)d_in[0];          // [B,T,D] f32
    const float*        W     = (const float*)d_in[1];          // [G,D,OUT] f32
    const float*        bias  = (const float*)d_in[2];          // [G,OUT] f32
    const int*          types = (const int*)d_in[3];            // [T] i32
    const unsigned int* pad   = (const unsigned int*)d_in[4];   // [B,T] mask words
    float*              out   = (float*)d_out;                  // [B,G,OUT] f32

    k_partial<<<dim3(NC, BB), 128>>>(batch, types, pad);
    k_mean<<<BB * GG, 128>>>();
    k_gemm<<<dim3(OO / 128, BB / 4, GG), 256>>>(W, bias, out);
}

// round 7
// speedup vs baseline: 5.2955x; 1.0284x over previous
#include <cuda_runtime.h>
#include <cstdint>

#define BB 32
#define TT 4096
#define DD 512
#define GG 8
#define OO 512
#define NC 32           // chunks over T
#define TC (TT/NC)      // 128 tokens per chunk

// Scratch (allocation-free: __device__ globals). Fully overwritten every launch.
__device__ float g_psum[NC * BB * GG * DD];   // 16.8 MB partial sums
__device__ int   g_pcnt[NC * BB * GG];        // partial counts
__device__ float g_mean[BB * GG * DD];        // means [B,G,D]

// ---------------------------------------------------------------------------
// Kernel 1: per-(chunk, batch) partial group sums.
// Two-pass compaction -> ONE concatenated group-ordered list; gather runs a
// continuous 8-deep software pipeline across ALL valid tokens (no per-group
// pipeline drains). Boundary handling is warp-uniform.
// ---------------------------------------------------------------------------
__global__ __launch_bounds__(128) void k_partial(const float* __restrict__ batch,
                                                 const int* __restrict__ types,
                                                 const unsigned int* __restrict__ pad)
{
    __shared__ int            s_type[TC];
    __shared__ unsigned char  s_val[TC];
    __shared__ unsigned short s_all[TC];    // concatenated valid tokens, group-ordered
    __shared__ int            s_boff[GG + 1];
    __shared__ int            s_cnt[GG];

    const int c   = blockIdx.x;
    const int b   = blockIdx.y;
    const int tid = threadIdx.x;
    const int t0  = c * TC;

    s_type[tid] = types[t0 + tid];
    s_val[tid]  = (pad[b * TT + t0 + tid] == 0u);   // valid = not padded
    __syncthreads();

    if (tid < 32) {
        const unsigned lt = (1u << tid) - 1u;
        int cnt[GG];
        #pragma unroll
        for (int g = 0; g < GG; g++) cnt[g] = 0;

        // pass 1: counts per group
        #pragma unroll
        for (int r = 0; r < TC / 32; r++) {
            const int  t  = r * 32 + tid;
            const int  gt = s_type[t];
            const bool v  = (s_val[t] != 0);
            #pragma unroll
            for (int g = 0; g < GG; g++)
                cnt[g] += __popc(__ballot_sync(0xffffffffu, v && (gt == g)));
        }
        // exclusive prefix -> bases
        int run[GG];
        {
            int acc = 0;
            #pragma unroll
            for (int g = 0; g < GG; g++) { run[g] = acc; acc += cnt[g]; }
            if (tid == 0) {
                int a2 = 0;
                #pragma unroll
                for (int g = 0; g < GG; g++) { s_boff[g] = a2; s_cnt[g] = cnt[g]; a2 += cnt[g]; }
                s_boff[GG] = a2;
            }
        }
        // pass 2: scatter token ids into concatenated list
        #pragma unroll
        for (int r = 0; r < TC / 32; r++) {
            const int  t  = r * 32 + tid;
            const int  gt = s_type[t];
            const bool v  = (s_val[t] != 0);
            #pragma unroll
            for (int g = 0; g < GG; g++) {
                const unsigned m = __ballot_sync(0xffffffffu, v && (gt == g));
                if (v && (gt == g))
                    s_all[run[g] + __popc(m & lt)] = (unsigned short)t;
                run[g] += __popc(m);
            }
        }
    }
    __syncthreads();

    const float4* bp2 = reinterpret_cast<const float4*>(batch)
                      + (size_t)b * TT * (DD / 4) + (size_t)t0 * (DD / 4) + tid;
    float4* outp = reinterpret_cast<float4*>(g_psum)
                 + (size_t)(c * BB + b) * GG * (DD / 4);

    const int n = s_boff[GG];

    float4 buf[8];
    #pragma unroll
    for (int k = 0; k < 8; k++)
        buf[k] = (k < n) ? __ldcs(&bp2[(int)s_all[k] * 128])
                         : make_float4(0.f, 0.f, 0.f, 0.f);

    int   g   = 0;
    int   nb  = s_boff[1];
    float4 acc = make_float4(0.f, 0.f, 0.f, 0.f);

    // flush any leading empty groups (boundary at 0)
    while (g < GG && nb == 0) {
        outp[g * (DD / 4) + tid] = acc;
        g++;
        nb = (g < GG) ? s_boff[g + 1] : 0x7fffffff;
    }

    int i = 0;
    // steady state: consume 8, load next 8 (all in-range)
    for (; i + 16 <= n; i += 8) {
        #pragma unroll
        for (int k = 0; k < 8; k++) {
            const float4 v = buf[k];
            buf[k] = __ldcs(&bp2[(int)s_all[i + 8 + k] * 128]);
            acc.x += v.x; acc.y += v.y; acc.z += v.z; acc.w += v.w;
            const int idx1 = i + k + 1;
            while (g < GG && idx1 == nb) {
                outp[g * (DD / 4) + tid] = acc;
                acc = make_float4(0.f, 0.f, 0.f, 0.f);
                g++;
                nb = (g < GG) ? s_boff[g + 1] : 0x7fffffff;
            }
        }
    }
    // penultimate batch: consume 8, load remaining (<8)
    for (; i + 8 <= n; i += 8) {
        #pragma unroll
        for (int k = 0; k < 8; k++) {
            const float4 v = buf[k];
            const int j = i + 8 + k;
            if (j < n) buf[k] = __ldcs(&bp2[(int)s_all[j] * 128]);
            acc.x += v.x; acc.y += v.y; acc.z += v.z; acc.w += v.w;
            const int idx1 = i + k + 1;
            while (g < GG && idx1 == nb) {
                outp[g * (DD / 4) + tid] = acc;
                acc = make_float4(0.f, 0.f, 0.f, 0.f);
                g++;
                nb = (g < GG) ? s_boff[g + 1] : 0x7fffffff;
            }
        }
    }
    // tail: consume remaining (<8) from buf
    #pragma unroll
    for (int k = 0; k < 8; k++) {
        if (i + k < n) {
            const float4 v = buf[k];
            acc.x += v.x; acc.y += v.y; acc.z += v.z; acc.w += v.w;
            const int idx1 = i + k + 1;
            while (g < GG && idx1 == nb) {
                outp[g * (DD / 4) + tid] = acc;
                acc = make_float4(0.f, 0.f, 0.f, 0.f);
                g++;
                nb = (g < GG) ? s_boff[g + 1] : 0x7fffffff;
            }
        }
    }
    // safety: flush trailing groups (handles n==0 etc.)
    while (g < GG) {
        outp[g * (DD / 4) + tid] = acc;
        acc = make_float4(0.f, 0.f, 0.f, 0.f);
        g++;
    }

    if (tid < GG) g_pcnt[(c * BB + b) * GG + tid] = s_cnt[tid];
}

// ---------------------------------------------------------------------------
// Kernel 2: reduce psum -> mean, once. 256 blocks x 128 (MLP 32 per thread).
// ---------------------------------------------------------------------------
__global__ __launch_bounds__(128) void k_mean()
{
    const int bg  = blockIdx.x;     // b*GG+g
    const int tid = threadIdx.x;

    __shared__ float s_inv;
    if (tid == 0) {
        int cnt = 0;
        #pragma unroll
        for (int c = 0; c < NC; c++) cnt += g_pcnt[c * BB * GG + bg];
        s_inv = (cnt > 0) ? (1.0f / (float)cnt) : 0.0f;
    }
    __syncthreads();

    const float4* p = reinterpret_cast<const float4*>(g_psum) + (size_t)bg * (DD / 4) + tid;
    float4 s = make_float4(0.f, 0.f, 0.f, 0.f);
    #pragma unroll
    for (int c = 0; c < NC; c++) {
        const float4 v = p[(size_t)c * BB * GG * (DD / 4)];
        s.x += v.x; s.y += v.y; s.z += v.z; s.w += v.w;
    }
    const float inv = s_inv;
    reinterpret_cast<float4*>(g_mean)[(size_t)bg * (DD / 4) + tid] =
        make_float4(s.x * inv, s.y * inv, s.z * inv, s.w * inv);
}

// ---------------------------------------------------------------------------
// Kernel 3: GEMM. grid (4 ot x 8 bo x 8 g) = 256 blocks, 256 threads.
// Warp w owns d in [64w, 64w+64); register-blocks 4 b's x 1 o-float4.
// ---------------------------------------------------------------------------
__global__ __launch_bounds__(256) void k_gemm(const float* __restrict__ W,
                                              const float* __restrict__ bias,
                                              float* __restrict__ out)
{
    const int ot   = blockIdx.x;          // 128-output o-tile
    const int bo   = blockIdx.y;          // batch quad (4 b)
    const int g    = blockIdx.z;
    const int tid  = threadIdx.x;
    const int warp = tid >> 5;            // d-slice owner
    const int lane = tid & 31;            // o-float4 in tile

    __shared__ float  s_mean[4][DD];      // 8 KB
    __shared__ float4 s_part[8][4][32];   // 16 KB

    {
        float4* sm4 = reinterpret_cast<float4*>(s_mean);
        const float4* gm4 = reinterpret_cast<const float4*>(g_mean);
        #pragma unroll
        for (int k = 0; k < 2; k++) {
            const int idx = tid + k * 256;                 // 0..511
            const int bb  = idx >> 7;                      // 0..3
            const int d4  = idx & 127;
            sm4[idx] = gm4[((size_t)(bo * 4 + bb) * GG + g) * (DD / 4) + d4];
        }
    }
    __syncthreads();

    const float4* W4 = reinterpret_cast<const float4*>(W)
                     + (size_t)g * DD * (OO / 4) + ot * 32 + lane;

    float4 a0 = make_float4(0.f, 0.f, 0.f, 0.f);
    float4 a1 = make_float4(0.f, 0.f, 0.f, 0.f);
    float4 a2 = make_float4(0.f, 0.f, 0.f, 0.f);
    float4 a3 = make_float4(0.f, 0.f, 0.f, 0.f);

    const int d0 = warp * 64;
    #pragma unroll 8
    for (int dd = 0; dd < 64; dd++) {
        const int d = d0 + dd;
        const float4 w = W4[(size_t)d * (OO / 4)];
        const float m0 = s_mean[0][d];
        const float m1 = s_mean[1][d];
        const float m2 = s_mean[2][d];
        const float m3 = s_mean[3][d];
        a0.x += m0 * w.x; a0.y += m0 * w.y; a0.z += m0 * w.z; a0.w += m0 * w.w;
        a1.x += m1 * w.x; a1.y += m1 * w.y; a1.z += m1 * w.z; a1.w += m1 * w.w;
        a2.x += m2 * w.x; a2.y += m2 * w.y; a2.z += m2 * w.z; a2.w += m2 * w.w;
        a3.x += m3 * w.x; a3.y += m3 * w.y; a3.z += m3 * w.z; a3.w += m3 * w.w;
    }

    s_part[warp][0][lane] = a0;
    s_part[warp][1][lane] = a1;
    s_part[warp][2][lane] = a2;
    s_part[warp][3][lane] = a3;
    __syncthreads();

    if (tid < 128) {
        const int b = tid >> 5;
        const int l = tid & 31;
        float4 s = make_float4(0.f, 0.f, 0.f, 0.f);
        #pragma unroll
        for (int w = 0; w < 8; w++) {
            const float4 v = s_part[w][b][l];
            s.x += v.x; s.y += v.y; s.z += v.z; s.w += v.w;
        }
        const float4 bi = reinterpret_cast<const float4*>(bias)[g * (OO / 4) + ot * 32 + l];
        const size_t obg = (size_t)((bo * 4 + b) * GG + g);
        reinterpret_cast<float4*>(out)[obg * (OO / 4) + ot * 32 + l] =
            make_float4(s.x + bi.x, s.y + bi.y, s.z + bi.z, s.w + bi.w);
    }
}

// ---------------------------------------------------------------------------
extern "C" void kernel_launch(void* const* d_in, const int* in_sizes, int n_in,
                              void* d_out, int out_size)
{
    const float*        batch = (const float*)d_in[0];          // [B,T,D] f32
    const float*        W     = (const float*)d_in[1];          // [G,D,OUT] f32
    const float*        bias  = (const float*)d_in[2];          // [G,OUT] f32
    const int*          types = (const int*)d_in[3];            // [T] i32
    const unsigned int* pad   = (const unsigned int*)d_in[4];   // [B,T] mask words
    float*              out   = (float*)d_out;                  // [B,G,OUT] f32

    k_partial<<<dim3(NC, BB), 128>>>(batch, types, pad);
    k_mean<<<BB * GG, 128>>>();
    k_gemm<<<dim3(OO / 128, BB / 4, GG), 256>>>(W, bias, out);
}